// round 11
// baseline (speedup 1.0000x reference)
#include <cuda_runtime.h>
#include <math.h>

#define BMAX     256
#define SIGLEN   178
#define NFR      43
#define NFQ      33
#define NPQ      (NFQ*NFR)
#define COUT     64
#define CONV_OUT 89
#define NSTEP    12          // ceil(89/8) j-steps

#define PHI_N    (89*4*7*64)
#define AY_N     (89*4*7)
#define TW_N     (33*7)

__device__ __align__(16) float g_spec2[NPQ * BMAX * 2];      // [p*43+q][b dup x2]
__device__ __align__(16) float g_phi  [PHI_N];               // [j][qt][ky][c]
__device__ __align__(16) float g_ay   [AY_N];                // [r][pt][ky]
__device__ __align__(16) float g_twid [33*14];
__device__ __align__(16) float g_theta[(size_t)89*89*16*64]; // [r][j][tap][c]
__device__ __align__(16) float g_part [(size_t)CONV_OUT * BMAX * COUT]; // [r][b][c]

// ---- shared index helpers --------------------------------------------------
__device__ __forceinline__ int q0raw(int j) {
    float sx = (2 * j - 3 + 0.5f) * (43.0f / 178.0f) - 0.5f;
    sx = fminf(fmaxf(sx, 0.f), 42.f);
    return (int)sx;
}
__device__ __forceinline__ int q0f(int j) { int q = q0raw(j); return q > 39 ? 39 : q; }
__device__ __forceinline__ int p0f(int r) {
    float sy = (2 * r - 3 + 0.5f) * (33.0f / 178.0f) - 0.5f;
    sy = fminf(fmaxf(sy, 0.f), 32.f);
    int p = (int)sy; return p > 29 ? 29 : p;
}
__device__ __forceinline__ float bweight(int x, int q) {
    if (x < 0 || x >= 178) return 0.f;
    float sx = fminf(fmaxf((x + 0.5f) * (43.0f / 178.0f) - 0.5f, 0.f), 42.f);
    int x0 = (int)sx; float fx = sx - (float)x0; int x1 = min(x0 + 1, 42);
    float w = 0.f;
    if (q == x0) w += 1.f - fx;
    if (q == x1) w += fx;
    return w;
}

#define UNPACK2(lo, hi, d) asm("mov.b64 {%0, %1}, %2;" : "=f"(lo), "=f"(hi) : "l"(d))
#define FFMA2(d, a, b) asm("fma.rn.f32x2 %0, %1, %2, %0;" : "+l"(d) : "l"(a), "l"(b))
#define LDSV2(a0, a1, ad) asm volatile("ld.shared.v2.b64 {%0, %1}, [%2];" \
                                       : "=l"(a0), "=l"(a1) : "r"(ad))
#define CPASYNC16(dst, src) asm volatile( \
    "cp.async.cg.shared.global [%0], [%1], 16;" :: "r"(dst), "l"(src))
#define CPCOMMIT() asm volatile("cp.async.commit_group;")
#define CPWAIT1()  asm volatile("cp.async.wait_group 1;")
#define CPWAIT0()  asm volatile("cp.async.wait_group 0;")

// ---- prep ------------------------------------------------------------------
__global__ void prep_kernel(const float* __restrict__ w) {
    int t = blockIdx.x * blockDim.x + threadIdx.x;
    if (t < PHI_N) {
        int c  = t & 63;
        int u  = t >> 6;
        int ky = u % 7;  u /= 7;
        int qt = u & 3;
        int j  = u >> 2;
        int q  = q0f(j) + qt;
        const float* wc = w + c * 147 + ky * 7;
        float a = 0.f;
#pragma unroll
        for (int kx = 0; kx < 7; kx++) {
            float ws = wc[kx] + wc[49 + kx] + wc[98 + kx];
            a += ws * bweight(2 * j - 3 + kx, q);
        }
        g_phi[((j * 4 + qt) * 7 + ky) * 64 + c] = a;
    } else if (t < PHI_N + AY_N) {
        int t2 = t - PHI_N;
        int r = t2 / 28, rem = t2 % 28, pt = rem / 7, ky = rem % 7;
        int y = 2 * r - 3 + ky;
        float wgt = 0.f;
        if (y >= 0 && y < 178) {
            float sy = fminf(fmaxf((y + 0.5f) * (33.0f / 178.0f) - 0.5f, 0.f), 32.f);
            int y0 = (int)sy; float fy = sy - (float)y0; int y1 = min(y0 + 1, 32);
            int p = p0f(r) + pt;
            if (p == y0) wgt += 1.f - fy;
            if (p == y1) wgt += fy;
        }
        g_ay[t2] = wgt;
    } else if (t < PHI_N + AY_N + TW_N) {
        int t3 = t - PHI_N - AY_N;
        int k = t3 / 7, n = 1 + t3 % 7;
        float sn, cs;
        sincospif((float)(k * n) * (1.0f / 32.0f), &sn, &cs);
        g_twid[k * 14 + (n - 1) * 2]     = cs;
        g_twid[k * 14 + (n - 1) * 2 + 1] = sn;
    }
}

// ---- spectrogram (writes duplicated pairs) ---------------------------------
__global__ void spec_kernel(const float* __restrict__ x, int B) {
    int pq = blockIdx.x;
    int b  = threadIdx.x;
    if (b >= B) return;
    int k  = pq / NFR;
    int fr = pq % NFR;

    const float* s = x + b * SIGLEN + fr * 4;
    float v[8];
    float mean = 0.f;
#pragma unroll
    for (int n = 0; n < 8; n++) { v[n] = s[n]; mean += v[n]; }
    mean *= 0.125f;

    const float* tw = g_twid + k * 14;
    float re = 0.f, im = 0.f;
#pragma unroll
    for (int n = 1; n < 8; n++) {
        float f = v[n] - mean;
        re = fmaf(f, tw[(n - 1) * 2], re);
        im = fmaf(f, -tw[(n - 1) * 2 + 1], im);
    }
    const float SCALE = sqrtf(1.0f / (178.0f * 7.0f));
    float val = sqrtf(re * re + im * im) * SCALE;
    float2* dst = (float2*)(g_spec2 + (size_t)pq * (BMAX * 2));
    dst[b] = make_float2(val, val);
}

// ---- theta: Theta[r][j][tap][c], tap = pt*4+qt -----------------------------
__global__ void theta_kernel() {
    int j  = blockIdx.x;
    int r0 = blockIdx.y * 4;
    int tid = threadIdx.x;
    int c = tid & 63, qt = tid >> 6;

    float f[7];
#pragma unroll
    for (int ky = 0; ky < 7; ky++)
        f[ky] = g_phi[((j * 4 + qt) * 7 + ky) * 64 + c];

#pragma unroll
    for (int rr = 0; rr < 4; rr++) {
        int r = r0 + rr;
        if (r >= CONV_OUT) break;
        const float* ay = g_ay + r * 28;
        float* dst = g_theta + (size_t)(r * 89 + j) * 1024;
#pragma unroll
        for (int pt = 0; pt < 4; pt++) {
            float th = 0.f;
#pragma unroll
            for (int ky = 0; ky < 7; ky++)
                th = fmaf(ay[pt * 7 + ky], f[ky], th);
            dst[(pt * 4 + qt) * 64 + c] = th;
        }
    }
}

// ---- main tap: cp.async Θ pipeline, c-pair multipliers ---------------------
// block = (r, 16 batches); warp w: j = step*8 + w
__global__ void __launch_bounds__(256, 2)
tap_kernel(const float* __restrict__ bias, int B) {
    extern __shared__ float smem_raw[];   // 64 KB: 2 buffers x 8 slabs x 4KB
    int tid  = threadIdx.x;
    int lane = tid & 31, w = tid >> 5;
    int qd   = lane & 15, bh = lane >> 4;

    int item   = blockIdx.x;              // r * 16 + bchunk
    int r      = item >> 4;
    int bchunk = item & 15;
    int b0     = bchunk * 16 + bh * 8;
    int c0     = qd * 4;

    unsigned sb;
    asm("{ .reg .u64 t; cvta.to.shared.u64 t, %1; cvt.u32.u64 %0, t; }"
        : "=r"(sb) : "l"(smem_raw));

    int p0 = p0f(r);
    const float* sprow = g_spec2 + (size_t)(p0 * NFR) * (BMAX * 2) + b0 * 2;

    ulonglong2 bp = *(const ulonglong2*)(bias + c0);  // (c0,c1),(c2,c3) pairs

    float acc[4][8];
#pragma unroll
    for (int ci = 0; ci < 4; ci++)
#pragma unroll
        for (int k = 0; k < 8; k++) acc[ci][k] = 0.f;

    const char* tbase = (const char*)(g_theta + (size_t)r * (89 * 1024));

#define STAGE(s, buf) do {                                                  \
        int _s = (s);                                                       \
        unsigned _d = sb + (unsigned)((buf) * 32768 + tid * 16);            \
        _Pragma("unroll")                                                   \
        for (int k = 0; k < 8; k++) {                                       \
            int jk = _s * 8 + k;                                            \
            if (jk < CONV_OUT)                                              \
                CPASYNC16(_d + (unsigned)(k * 4096),                        \
                          tbase + (size_t)jk * 4096 + tid * 16);            \
        }                                                                   \
    } while (0)

    STAGE(0, 0); CPCOMMIT();

    for (int s = 0; s < NSTEP; s++) {
        if (s + 1 < NSTEP) { STAGE(s + 1, (s + 1) & 1); CPCOMMIT(); CPWAIT1(); }
        else               { CPWAIT0(); }
        __syncthreads();

        int j = s * 8 + w;
        if (j < CONV_OUT) {
            int q0 = q0f(j);
            const float* sp = sprow + (size_t)q0 * (BMAX * 2);
            unsigned slab = sb + (unsigned)(((s & 1) * 32768) + w * 4096 + qd * 16);

            unsigned long long d[2][8];
#pragma unroll
            for (int bi = 0; bi < 8; bi++) { d[0][bi] = bp.x; d[1][bi] = bp.y; }

#pragma unroll
            for (int pt = 0; pt < 4; pt++) {
#pragma unroll
                for (int qt = 0; qt < 4; qt++) {
                    int t = pt * 4 + qt;
                    unsigned long long T0, T1;           // (c0,c1),(c2,c3)
                    LDSV2(T0, T1, slab + (unsigned)(t * 256));
                    const ulonglong2* s2 = (const ulonglong2*)
                        (sp + (size_t)(pt * NFR + qt) * (BMAX * 2));
                    ulonglong2 u0 = __ldg(s2);           // b0,b1 dup
                    ulonglong2 u1 = __ldg(s2 + 1);       // b2,b3 dup
                    ulonglong2 u2 = __ldg(s2 + 2);       // b4,b5 dup
                    ulonglong2 u3 = __ldg(s2 + 3);       // b6,b7 dup
                    FFMA2(d[0][0], T0, u0.x); FFMA2(d[1][0], T1, u0.x);
                    FFMA2(d[0][1], T0, u0.y); FFMA2(d[1][1], T1, u0.y);
                    FFMA2(d[0][2], T0, u1.x); FFMA2(d[1][2], T1, u1.x);
                    FFMA2(d[0][3], T0, u1.y); FFMA2(d[1][3], T1, u1.y);
                    FFMA2(d[0][4], T0, u2.x); FFMA2(d[1][4], T1, u2.x);
                    FFMA2(d[0][5], T0, u2.y); FFMA2(d[1][5], T1, u2.y);
                    FFMA2(d[0][6], T0, u3.x); FFMA2(d[1][6], T1, u3.x);
                    FFMA2(d[0][7], T0, u3.y); FFMA2(d[1][7], T1, u3.y);
                }
            }
            // scalar relu + GAP accumulate
#pragma unroll
            for (int bi = 0; bi < 8; bi++) {
                float x0, x1, x2, x3;
                UNPACK2(x0, x1, d[0][bi]);
                UNPACK2(x2, x3, d[1][bi]);
                acc[0][bi] += fmaxf(x0, 0.f);
                acc[1][bi] += fmaxf(x1, 0.f);
                acc[2][bi] += fmaxf(x2, 0.f);
                acc[3][bi] += fmaxf(x3, 0.f);
            }
        }
        __syncthreads();
    }

    // ---- cross-warp reduce (8 j-streams -> one partial per (b,c)) ----------
    float4* rs = (float4*)smem_raw;       // [w][16 b][16 c-quads]
#pragma unroll
    for (int bi = 0; bi < 8; bi++)
        rs[w * 256 + (bh * 8 + bi) * 16 + qd] =
            make_float4(acc[0][bi], acc[1][bi], acc[2][bi], acc[3][bi]);
    __syncthreads();

    int ob  = tid >> 4;                   // 0..15 batch within chunk
    int oc4 = tid & 15;                   // c-quad
    float4 v = rs[ob * 16 + oc4];
#pragma unroll
    for (int ww = 1; ww < 8; ww++) {
        float4 u = rs[ww * 256 + ob * 16 + oc4];
        v.x += u.x; v.y += u.y; v.z += u.z; v.w += u.w;
    }
    int b = bchunk * 16 + ob;
    if (b < B)
        *(float4*)(g_part + ((size_t)r * BMAX + b) * COUT + oc4 * 4) = v;
}

// ---- final: sum partials over r + GAP mean + FC ----------------------------
__global__ void fc_kernel(const float* __restrict__ fw,
                          const float* __restrict__ fb,
                          float* __restrict__ out, int B) {
    __shared__ float sm[4][COUT];
    int b = blockIdx.x;
    int tid = threadIdx.x;
    int c = tid & 63, pg = tid >> 6;
    float sum = 0.f;
    for (int rr = pg; rr < CONV_OUT; rr += 4)
        sum += g_part[((size_t)rr * BMAX + b) * COUT + c];
    sm[pg][c] = sum;
    __syncthreads();
    if (tid < COUT)
        sm[0][tid] += sm[1][tid] + sm[2][tid] + sm[3][tid];
    __syncthreads();
    if (tid < 5) {
        const float inv = 1.0f / (float)(CONV_OUT * CONV_OUT);
        float accv = fb[tid];
#pragma unroll 8
        for (int c2 = 0; c2 < COUT; c2++)
            accv = fmaf(sm[0][c2] * inv, fw[tid * 64 + c2], accv);
        out[b * 5 + tid] = accv;
    }
}

// ---------------------------------------------------------------------------
extern "C" void kernel_launch(void* const* d_in, const int* in_sizes, int n_in,
                              void* d_out, int out_size) {
    const float* x      = (const float*)d_in[0];
    const float* conv_w = (const float*)d_in[1];
    const float* conv_b = (const float*)d_in[2];
    const float* fc_w   = (const float*)d_in[3];
    const float* fc_b   = (const float*)d_in[4];
    float*       out    = (float*)d_out;

    int B = in_sizes[0] / SIGLEN;
    if (B > BMAX) B = BMAX;

    cudaFuncSetAttribute(tap_kernel,
                         cudaFuncAttributeMaxDynamicSharedMemorySize, 65536);

    int prep_total = PHI_N + AY_N + TW_N;
    prep_kernel<<<(prep_total + 255) / 256, 256>>>(conv_w);

    spec_kernel<<<NPQ, 256>>>(x, B);

    dim3 tgrid(89, 23);
    theta_kernel<<<tgrid, 256>>>();

    tap_kernel<<<CONV_OUT * 16, 256, 65536>>>(conv_b, B);

    fc_kernel<<<B, 256>>>(fc_w, fc_b, out, B);
}

// round 12
// speedup vs baseline: 1.3553x; 1.3553x over previous
#include <cuda_runtime.h>
#include <math.h>

#define BMAX     256
#define SIGLEN   178
#define NFR      43
#define NFQ      33
#define NPQ      (NFQ*NFR)
#define COUT     64
#define CONV_OUT 89
#define NSTEP    12          // ceil(89/8) j-steps

#define PHI_N    (89*4*7*64)
#define AY_N     (89*4*7)
#define TW_N     (33*7)

__device__ __align__(16) float g_spec [NPQ * BMAX];          // [p*43+q][b]
__device__ __align__(16) float g_phi  [PHI_N];               // [j][qt][ky][c]
__device__ __align__(16) float g_ay   [AY_N];                // [r][pt][ky]
__device__ __align__(16) float g_twid [33*14];
__device__ __align__(16) float g_theta[(size_t)89*89*16*64]; // [r][j][tap][c]
__device__ __align__(16) float g_part [(size_t)CONV_OUT * BMAX * COUT]; // [r][b][c]

// ---- shared index helpers --------------------------------------------------
__device__ __forceinline__ int q0raw(int j) {
    float sx = (2 * j - 3 + 0.5f) * (43.0f / 178.0f) - 0.5f;
    sx = fminf(fmaxf(sx, 0.f), 42.f);
    return (int)sx;
}
__device__ __forceinline__ int q0f(int j) { int q = q0raw(j); return q > 39 ? 39 : q; }
__device__ __forceinline__ int p0f(int r) {
    float sy = (2 * r - 3 + 0.5f) * (33.0f / 178.0f) - 0.5f;
    sy = fminf(fmaxf(sy, 0.f), 32.f);
    int p = (int)sy; return p > 29 ? 29 : p;
}
__device__ __forceinline__ float bweight(int x, int q) {
    if (x < 0 || x >= 178) return 0.f;
    float sx = fminf(fmaxf((x + 0.5f) * (43.0f / 178.0f) - 0.5f, 0.f), 42.f);
    int x0 = (int)sx; float fx = sx - (float)x0; int x1 = min(x0 + 1, 42);
    float w = 0.f;
    if (q == x0) w += 1.f - fx;
    if (q == x1) w += fx;
    return w;
}

#define PACK2(d, x)  asm("mov.b64 %0, {%1, %1};" : "=l"(d) : "f"(x))
#define PACKAB(d, a, b) asm("mov.b64 %0, {%1, %2};" : "=l"(d) : "f"(a), "f"(b))
#define UNPACK2(lo, hi, d) asm("mov.b64 {%0, %1}, %2;" : "=f"(lo), "=f"(hi) : "l"(d))
#define FFMA2(d, a, b) asm("fma.rn.f32x2 %0, %1, %2, %0;" : "+l"(d) : "l"(a), "l"(b))
#define ADD2(acc, v) asm("add.rn.f32x2 %0, %0, %1;" : "+l"(acc) : "l"(v))
#define CPASYNC16(dst, src) asm volatile( \
    "cp.async.cg.shared.global [%0], [%1], 16;" :: "r"(dst), "l"(src))
#define CPCOMMIT() asm volatile("cp.async.commit_group;")
#define CPWAIT0()  asm volatile("cp.async.wait_group 0;")

// ---- prep ------------------------------------------------------------------
__global__ void prep_kernel(const float* __restrict__ w) {
    int t = blockIdx.x * blockDim.x + threadIdx.x;
    if (t < PHI_N) {
        int c  = t & 63;
        int u  = t >> 6;
        int ky = u % 7;  u /= 7;
        int qt = u & 3;
        int j  = u >> 2;
        int q  = q0f(j) + qt;
        const float* wc = w + c * 147 + ky * 7;
        float a = 0.f;
#pragma unroll
        for (int kx = 0; kx < 7; kx++) {
            float ws = wc[kx] + wc[49 + kx] + wc[98 + kx];
            a += ws * bweight(2 * j - 3 + kx, q);
        }
        g_phi[((j * 4 + qt) * 7 + ky) * 64 + c] = a;
    } else if (t < PHI_N + AY_N) {
        int t2 = t - PHI_N;
        int r = t2 / 28, rem = t2 % 28, pt = rem / 7, ky = rem % 7;
        int y = 2 * r - 3 + ky;
        float wgt = 0.f;
        if (y >= 0 && y < 178) {
            float sy = fminf(fmaxf((y + 0.5f) * (33.0f / 178.0f) - 0.5f, 0.f), 32.f);
            int y0 = (int)sy; float fy = sy - (float)y0; int y1 = min(y0 + 1, 32);
            int p = p0f(r) + pt;
            if (p == y0) wgt += 1.f - fy;
            if (p == y1) wgt += fy;
        }
        g_ay[t2] = wgt;
    } else if (t < PHI_N + AY_N + TW_N) {
        int t3 = t - PHI_N - AY_N;
        int k = t3 / 7, n = 1 + t3 % 7;
        float sn, cs;
        sincospif((float)(k * n) * (1.0f / 32.0f), &sn, &cs);
        g_twid[k * 14 + (n - 1) * 2]     = cs;
        g_twid[k * 14 + (n - 1) * 2 + 1] = sn;
    }
}

// ---- spectrogram -----------------------------------------------------------
__global__ void spec_kernel(const float* __restrict__ x, int B) {
    int pq = blockIdx.x;
    int b  = threadIdx.x;
    if (b >= B) return;
    int k  = pq / NFR;
    int fr = pq % NFR;

    const float* s = x + b * SIGLEN + fr * 4;
    float v[8];
    float mean = 0.f;
#pragma unroll
    for (int n = 0; n < 8; n++) { v[n] = s[n]; mean += v[n]; }
    mean *= 0.125f;

    const float* tw = g_twid + k * 14;
    float re = 0.f, im = 0.f;
#pragma unroll
    for (int n = 1; n < 8; n++) {
        float f = v[n] - mean;
        re = fmaf(f, tw[(n - 1) * 2], re);
        im = fmaf(f, -tw[(n - 1) * 2 + 1], im);
    }
    const float SCALE = sqrtf(1.0f / (178.0f * 7.0f));
    g_spec[pq * BMAX + b] = sqrtf(re * re + im * im) * SCALE;
}

// ---- theta: Theta[r][j][tap][c], tap = pt*4+qt -----------------------------
__global__ void theta_kernel() {
    int j  = blockIdx.x;
    int r0 = blockIdx.y * 4;
    int tid = threadIdx.x;
    int c = tid & 63, qt = tid >> 6;

    float f[7];
#pragma unroll
    for (int ky = 0; ky < 7; ky++)
        f[ky] = g_phi[((j * 4 + qt) * 7 + ky) * 64 + c];

#pragma unroll
    for (int rr = 0; rr < 4; rr++) {
        int r = r0 + rr;
        if (r >= CONV_OUT) break;
        const float* ay = g_ay + r * 28;
        float* dst = g_theta + (size_t)(r * 89 + j) * 1024;
#pragma unroll
        for (int pt = 0; pt < 4; pt++) {
            float th = 0.f;
#pragma unroll
            for (int ky = 0; ky < 7; ky++)
                th = fmaf(ay[pt * 7 + ky], f[ky], th);
            dst[(pt * 4 + qt) * 64 + c] = th;
        }
    }
}

// ---- main tap: cp.async Θ pipeline, 8 j-streams, 4c x 8b threads -----------
// block = (r, 16 batches); warp w handles j = step*8 + w.  One barrier/step.
__global__ void __launch_bounds__(256, 2)
tap_kernel(const float* __restrict__ bias, int B) {
    extern __shared__ float smem_raw[];   // 64 KB: 2 buffers x 8 slabs x 4KB
    int tid  = threadIdx.x;
    int lane = tid & 31, w = tid >> 5;
    int qd   = lane & 15, bh = lane >> 4;

    int item   = blockIdx.x;              // r * 16 + bchunk
    int r      = item >> 4;
    int bchunk = item & 15;
    int b0     = bchunk * 16 + bh * 8;
    int c0     = qd * 4;

    unsigned sb;
    asm("{ .reg .u64 t; cvta.to.shared.u64 t, %1; cvt.u32.u64 %0, t; }"
        : "=r"(sb) : "l"(smem_raw));

    int p0 = p0f(r);
    const float* sprow = g_spec + (p0 * NFR) * BMAX + b0;

    float4 b4 = *(const float4*)(bias + c0);
    unsigned long long bb[4];
    PACK2(bb[0], b4.x); PACK2(bb[1], b4.y);
    PACK2(bb[2], b4.z); PACK2(bb[3], b4.w);

    // packed (b-pair) GAP accumulators: acc2[c 0..3][b-pair 0..3]
    unsigned long long acc2[4][4];
#pragma unroll
    for (int ci = 0; ci < 4; ci++)
#pragma unroll
        for (int bi = 0; bi < 4; bi++) acc2[ci][bi] = 0ull;

    const float* tsrc_base = g_theta + (size_t)r * (89 * 1024) + tid * 4;

#define STAGE(s, buf) do {                                                  \
        int _s = (s);                                                       \
        unsigned _d = sb + (unsigned)((buf) * 32768 + tid * 16);            \
        _Pragma("unroll")                                                   \
        for (int k = 0; k < 8; k++) {                                       \
            int jk = _s * 8 + k;                                            \
            if (jk < CONV_OUT)                                              \
                CPASYNC16(_d + (unsigned)(k * 4096),                        \
                          tsrc_base + (size_t)jk * 1024);                   \
        }                                                                   \
    } while (0)

    STAGE(0, 0); CPCOMMIT();

    for (int s = 0; s < NSTEP; s++) {
        CPWAIT0();                        // own stage(s) copies done
        __syncthreads();                  // publish stage(s); free buf (s+1)&1
        if (s + 1 < NSTEP) { STAGE(s + 1, (s + 1) & 1); CPCOMMIT(); }

        int j = s * 8 + w;
        if (j < CONV_OUT) {
            int q0 = q0f(j);
            const float* sp = sprow + q0 * BMAX;
            const float4* slab = (const float4*)
                ((const char*)smem_raw + ((s & 1) * 32768) + w * 4096) + qd;

            unsigned long long d[4][4];
#pragma unroll
            for (int ci = 0; ci < 4; ci++)
#pragma unroll
                for (int bi = 0; bi < 4; bi++) d[ci][bi] = bb[ci];

#pragma unroll
            for (int pt = 0; pt < 4; pt++) {
#pragma unroll
                for (int qt = 0; qt < 4; qt++) {
                    int t = pt * 4 + qt;
                    float4 wv = slab[t * 16];
                    const ulonglong2* s2 =
                        (const ulonglong2*)(sp + (pt * NFR + qt) * BMAX);
                    ulonglong2 u0 = __ldg(s2);
                    ulonglong2 u1 = __ldg(s2 + 1);
                    unsigned long long W0, W1, W2, W3;
                    PACK2(W0, wv.x); PACK2(W1, wv.y);
                    PACK2(W2, wv.z); PACK2(W3, wv.w);
                    FFMA2(d[0][0], W0, u0.x); FFMA2(d[0][1], W0, u0.y);
                    FFMA2(d[0][2], W0, u1.x); FFMA2(d[0][3], W0, u1.y);
                    FFMA2(d[1][0], W1, u0.x); FFMA2(d[1][1], W1, u0.y);
                    FFMA2(d[1][2], W1, u1.x); FFMA2(d[1][3], W1, u1.y);
                    FFMA2(d[2][0], W2, u0.x); FFMA2(d[2][1], W2, u0.y);
                    FFMA2(d[2][2], W2, u1.x); FFMA2(d[2][3], W2, u1.y);
                    FFMA2(d[3][0], W3, u0.x); FFMA2(d[3][1], W3, u0.y);
                    FFMA2(d[3][2], W3, u1.x); FFMA2(d[3][3], W3, u1.y);
                }
            }
            // relu (alu-pipe FMNMX) + packed GAP add (halves fma-pipe adds)
#pragma unroll
            for (int ci = 0; ci < 4; ci++)
#pragma unroll
                for (int bi = 0; bi < 4; bi++) {
                    float lo, hi; UNPACK2(lo, hi, d[ci][bi]);
                    lo = fmaxf(lo, 0.f); hi = fmaxf(hi, 0.f);
                    unsigned long long m; PACKAB(m, lo, hi);
                    ADD2(acc2[ci][bi], m);
                }
        }
    }
    __syncthreads();   // protect smem reuse below against last-step stragglers

    // ---- cross-warp reduce (8 j-streams -> one partial per (b,c)) ----------
    float4* rs = (float4*)smem_raw;       // [w][16 b][16 c-quads]
#pragma unroll
    for (int bp = 0; bp < 4; bp++) {
        float a0, a1, b1v, b2v, c1, c2, d1, d2;
        UNPACK2(a0, a1, acc2[0][bp]);
        UNPACK2(b1v, b2v, acc2[1][bp]);
        UNPACK2(c1, c2, acc2[2][bp]);
        UNPACK2(d1, d2, acc2[3][bp]);
        rs[w * 256 + (bh * 8 + 2 * bp) * 16 + qd]     = make_float4(a0, b1v, c1, d1);
        rs[w * 256 + (bh * 8 + 2 * bp + 1) * 16 + qd] = make_float4(a1, b2v, c2, d2);
    }
    __syncthreads();

    int ob  = tid >> 4;                   // 0..15 batch within chunk
    int oc4 = tid & 15;                   // c-quad
    float4 v = rs[ob * 16 + oc4];
#pragma unroll
    for (int ww = 1; ww < 8; ww++) {
        float4 u = rs[ww * 256 + ob * 16 + oc4];
        v.x += u.x; v.y += u.y; v.z += u.z; v.w += u.w;
    }
    int b = bchunk * 16 + ob;
    if (b < B)
        *(float4*)(g_part + ((size_t)r * BMAX + b) * COUT + oc4 * 4) = v;
}

// ---- final: sum partials over r + GAP mean + FC ----------------------------
__global__ void fc_kernel(const float* __restrict__ fw,
                          const float* __restrict__ fb,
                          float* __restrict__ out, int B) {
    __shared__ float sm[4][COUT];
    int b = blockIdx.x;
    int tid = threadIdx.x;
    int c = tid & 63, pg = tid >> 6;
    float sum = 0.f;
    for (int rr = pg; rr < CONV_OUT; rr += 4)
        sum += g_part[((size_t)rr * BMAX + b) * COUT + c];
    sm[pg][c] = sum;
    __syncthreads();
    if (tid < COUT)
        sm[0][tid] += sm[1][tid] + sm[2][tid] + sm[3][tid];
    __syncthreads();
    if (tid < 5) {
        const float inv = 1.0f / (float)(CONV_OUT * CONV_OUT);
        float accv = fb[tid];
#pragma unroll 8
        for (int c2 = 0; c2 < COUT; c2++)
            accv = fmaf(sm[0][c2] * inv, fw[tid * 64 + c2], accv);
        out[b * 5 + tid] = accv;
    }
}

// ---------------------------------------------------------------------------
extern "C" void kernel_launch(void* const* d_in, const int* in_sizes, int n_in,
                              void* d_out, int out_size) {
    const float* x      = (const float*)d_in[0];
    const float* conv_w = (const float*)d_in[1];
    const float* conv_b = (const float*)d_in[2];
    const float* fc_w   = (const float*)d_in[3];
    const float* fc_b   = (const float*)d_in[4];
    float*       out    = (float*)d_out;

    int B = in_sizes[0] / SIGLEN;
    if (B > BMAX) B = BMAX;

    cudaFuncSetAttribute(tap_kernel,
                         cudaFuncAttributeMaxDynamicSharedMemorySize, 65536);

    int prep_total = PHI_N + AY_N + TW_N;
    prep_kernel<<<(prep_total + 255) / 256, 256>>>(conv_w);

    spec_kernel<<<NPQ, 256>>>(x, B);

    dim3 tgrid(89, 23);
    theta_kernel<<<tgrid, 256>>>();

    tap_kernel<<<CONV_OUT * 16, 256, 65536>>>(conv_b, B);

    fc_kernel<<<B, 256>>>(fc_w, fc_b, out, B);
}

// round 13
// speedup vs baseline: 1.4470x; 1.0676x over previous
#include <cuda_runtime.h>
#include <cuda_bf16.h>
#include <math.h>

#define BMAX     256
#define SIGLEN   178
#define NFR      43
#define NFQ      33
#define NPQ      (NFQ*NFR)
#define COUT     64
#define CONV_OUT 89
#define NSTEP    12          // ceil(89/8) j-steps

#define PHI_N    (89*4*7*64)
#define AY_N     (89*4*7)
#define TW_N     (33*7)

__device__ __align__(16) float g_spec [NPQ * BMAX];          // [p*43+q][b]
__device__ __align__(16) float g_phi  [PHI_N];               // [j][qt][ky][c]
__device__ __align__(16) float g_ay   [AY_N];                // [r][pt][ky]
__device__ __align__(16) float g_twid [33*14];
__device__ __align__(16) __nv_bfloat16 g_thetah[(size_t)89*89*16*64]; // [r][j][tap][c]
__device__ __align__(16) float g_part [(size_t)CONV_OUT * BMAX * COUT]; // [r][b][c]

// ---- shared index helpers --------------------------------------------------
__device__ __forceinline__ int q0raw(int j) {
    float sx = (2 * j - 3 + 0.5f) * (43.0f / 178.0f) - 0.5f;
    sx = fminf(fmaxf(sx, 0.f), 42.f);
    return (int)sx;
}
__device__ __forceinline__ int q0f(int j) { int q = q0raw(j); return q > 39 ? 39 : q; }
__device__ __forceinline__ int p0f(int r) {
    float sy = (2 * r - 3 + 0.5f) * (33.0f / 178.0f) - 0.5f;
    sy = fminf(fmaxf(sy, 0.f), 32.f);
    int p = (int)sy; return p > 29 ? 29 : p;
}
__device__ __forceinline__ float bweight(int x, int q) {
    if (x < 0 || x >= 178) return 0.f;
    float sx = fminf(fmaxf((x + 0.5f) * (43.0f / 178.0f) - 0.5f, 0.f), 42.f);
    int x0 = (int)sx; float fx = sx - (float)x0; int x1 = min(x0 + 1, 42);
    float w = 0.f;
    if (q == x0) w += 1.f - fx;
    if (q == x1) w += fx;
    return w;
}

#define PACK2(d, x)  asm("mov.b64 %0, {%1, %1};" : "=l"(d) : "f"(x))
#define PACKAB(d, a, b) asm("mov.b64 %0, {%1, %2};" : "=l"(d) : "f"(a), "f"(b))
#define UNPACK2(lo, hi, d) asm("mov.b64 {%0, %1}, %2;" : "=f"(lo), "=f"(hi) : "l"(d))
#define FFMA2(d, a, b) asm("fma.rn.f32x2 %0, %1, %2, %0;" : "+l"(d) : "l"(a), "l"(b))
#define ADD2(acc, v) asm("add.rn.f32x2 %0, %0, %1;" : "+l"(acc) : "l"(v))
// bf16 lo/hi of a 32-bit word -> duplicated f32 pair (prmt shifts bf16<<16)
#define BF2DUP_LO(d, w) asm("{ .reg .b32 t; prmt.b32 t, %1, 0, 0x1044; " \
                            "mov.b64 %0, {t, t}; }" : "=l"(d) : "r"(w))
#define BF2DUP_HI(d, w) asm("{ .reg .b32 t; prmt.b32 t, %1, 0, 0x3244; " \
                            "mov.b64 %0, {t, t}; }" : "=l"(d) : "r"(w))
#define LDSV2U(a0, a1, ad) asm volatile("ld.shared.v2.u32 {%0, %1}, [%2];" \
                                        : "=r"(a0), "=r"(a1) : "r"(ad))
#define CPASYNC16(dst, src) asm volatile( \
    "cp.async.cg.shared.global [%0], [%1], 16;" :: "r"(dst), "l"(src))
#define CPCOMMIT() asm volatile("cp.async.commit_group;")
#define CPWAIT0()  asm volatile("cp.async.wait_group 0;")

// ---- prep ------------------------------------------------------------------
__global__ void prep_kernel(const float* __restrict__ w) {
    int t = blockIdx.x * blockDim.x + threadIdx.x;
    if (t < PHI_N) {
        int c  = t & 63;
        int u  = t >> 6;
        int ky = u % 7;  u /= 7;
        int qt = u & 3;
        int j  = u >> 2;
        int q  = q0f(j) + qt;
        const float* wc = w + c * 147 + ky * 7;
        float a = 0.f;
#pragma unroll
        for (int kx = 0; kx < 7; kx++) {
            float ws = wc[kx] + wc[49 + kx] + wc[98 + kx];
            a += ws * bweight(2 * j - 3 + kx, q);
        }
        g_phi[((j * 4 + qt) * 7 + ky) * 64 + c] = a;
    } else if (t < PHI_N + AY_N) {
        int t2 = t - PHI_N;
        int r = t2 / 28, rem = t2 % 28, pt = rem / 7, ky = rem % 7;
        int y = 2 * r - 3 + ky;
        float wgt = 0.f;
        if (y >= 0 && y < 178) {
            float sy = fminf(fmaxf((y + 0.5f) * (33.0f / 178.0f) - 0.5f, 0.f), 32.f);
            int y0 = (int)sy; float fy = sy - (float)y0; int y1 = min(y0 + 1, 32);
            int p = p0f(r) + pt;
            if (p == y0) wgt += 1.f - fy;
            if (p == y1) wgt += fy;
        }
        g_ay[t2] = wgt;
    } else if (t < PHI_N + AY_N + TW_N) {
        int t3 = t - PHI_N - AY_N;
        int k = t3 / 7, n = 1 + t3 % 7;
        float sn, cs;
        sincospif((float)(k * n) * (1.0f / 32.0f), &sn, &cs);
        g_twid[k * 14 + (n - 1) * 2]     = cs;
        g_twid[k * 14 + (n - 1) * 2 + 1] = sn;
    }
}

// ---- spectrogram -----------------------------------------------------------
__global__ void spec_kernel(const float* __restrict__ x, int B) {
    int pq = blockIdx.x;
    int b  = threadIdx.x;
    if (b >= B) return;
    int k  = pq / NFR;
    int fr = pq % NFR;

    const float* s = x + b * SIGLEN + fr * 4;
    float v[8];
    float mean = 0.f;
#pragma unroll
    for (int n = 0; n < 8; n++) { v[n] = s[n]; mean += v[n]; }
    mean *= 0.125f;

    const float* tw = g_twid + k * 14;
    float re = 0.f, im = 0.f;
#pragma unroll
    for (int n = 1; n < 8; n++) {
        float f = v[n] - mean;
        re = fmaf(f, tw[(n - 1) * 2], re);
        im = fmaf(f, -tw[(n - 1) * 2 + 1], im);
    }
    const float SCALE = sqrtf(1.0f / (178.0f * 7.0f));
    g_spec[pq * BMAX + b] = sqrtf(re * re + im * im) * SCALE;
}

// ---- theta: Theta[r][j][tap][c] in bf16, tap = pt*4+qt ---------------------
__global__ void theta_kernel() {
    int j  = blockIdx.x;
    int r0 = blockIdx.y * 4;
    int tid = threadIdx.x;
    int c = tid & 63, qt = tid >> 6;

    float f[7];
#pragma unroll
    for (int ky = 0; ky < 7; ky++)
        f[ky] = g_phi[((j * 4 + qt) * 7 + ky) * 64 + c];

#pragma unroll
    for (int rr = 0; rr < 4; rr++) {
        int r = r0 + rr;
        if (r >= CONV_OUT) break;
        const float* ay = g_ay + r * 28;
        __nv_bfloat16* dst = g_thetah + (size_t)(r * 89 + j) * 1024;
#pragma unroll
        for (int pt = 0; pt < 4; pt++) {
            float th = 0.f;
#pragma unroll
            for (int ky = 0; ky < 7; ky++)
                th = fmaf(ay[pt * 7 + ky], f[ky], th);
            dst[(pt * 4 + qt) * 64 + c] = __float2bfloat16(th);
        }
    }
}

// ---- main tap: cp.async bf16-Θ pipeline, 8 j-streams, 4c x 8b threads ------
// block = (r, 16 batches); warp w handles j = step*8 + w.
__global__ void __launch_bounds__(256, 2)
tap_kernel(const float* __restrict__ bias, int B) {
    extern __shared__ float smem_raw[];   // 32 KB: 2 buffers x 8 slabs x 2KB
    int tid  = threadIdx.x;
    int lane = tid & 31, w = tid >> 5;
    int qd   = lane & 15, bh = lane >> 4;

    int item   = blockIdx.x;              // r * 16 + bchunk
    int r      = item >> 4;
    int bchunk = item & 15;
    int b0     = bchunk * 16 + bh * 8;
    int c0     = qd * 4;

    unsigned sb;
    asm("{ .reg .u64 t; cvta.to.shared.u64 t, %1; cvt.u32.u64 %0, t; }"
        : "=r"(sb) : "l"(smem_raw));

    int p0 = p0f(r);
    const float* sprow = g_spec + (p0 * NFR) * BMAX + b0;

    float4 b4 = *(const float4*)(bias + c0);
    unsigned long long bb[4];
    PACK2(bb[0], b4.x); PACK2(bb[1], b4.y);
    PACK2(bb[2], b4.z); PACK2(bb[3], b4.w);

    unsigned long long acc2[4][4];
#pragma unroll
    for (int ci = 0; ci < 4; ci++)
#pragma unroll
        for (int bi = 0; bi < 4; bi++) acc2[ci][bi] = 0ull;

    const char* tbase = (const char*)(g_thetah + (size_t)r * (89 * 1024));

    // stage: 8 slabs x 2KB = 16KB/buffer; thread stages 4x16B
#define STAGE(s, buf) do {                                                  \
        int _s = (s);                                                       \
        _Pragma("unroll")                                                   \
        for (int r4 = 0; r4 < 4; r4++) {                                    \
            int ch = r4 * 256 + tid;                                        \
            int k = ch >> 7, inner = (ch & 127) * 16;                       \
            int jk = _s * 8 + k;                                            \
            if (jk < CONV_OUT)                                              \
                CPASYNC16(sb + (unsigned)((buf) * 16384 + ch * 16),         \
                          tbase + (size_t)jk * 2048 + inner);               \
        }                                                                   \
    } while (0)

    STAGE(0, 0); CPCOMMIT();

    for (int s = 0; s < NSTEP; s++) {
        CPWAIT0();
        __syncthreads();
        if (s + 1 < NSTEP) { STAGE(s + 1, (s + 1) & 1); CPCOMMIT(); }

        int j = s * 8 + w;
        if (j < CONV_OUT) {
            int q0 = q0f(j);
            const float* sp = sprow + q0 * BMAX;
            unsigned slab = sb + (unsigned)(((s & 1) * 16384) + w * 2048 + qd * 8);

            unsigned long long d[4][4];
#pragma unroll
            for (int ci = 0; ci < 4; ci++)
#pragma unroll
                for (int bi = 0; bi < 4; bi++) d[ci][bi] = bb[ci];

#pragma unroll
            for (int pt = 0; pt < 4; pt++) {
#pragma unroll
                for (int qt = 0; qt < 4; qt++) {
                    int t = pt * 4 + qt;
                    unsigned w0_, w1_;                   // 4 bf16 channels
                    LDSV2U(w0_, w1_, slab + (unsigned)(t * 128));
                    const ulonglong2* s2 =
                        (const ulonglong2*)(sp + (pt * NFR + qt) * BMAX);
                    ulonglong2 u0 = __ldg(s2);
                    ulonglong2 u1 = __ldg(s2 + 1);
                    unsigned long long W0, W1, W2, W3;
                    BF2DUP_LO(W0, w0_); BF2DUP_HI(W1, w0_);
                    BF2DUP_LO(W2, w1_); BF2DUP_HI(W3, w1_);
                    FFMA2(d[0][0], W0, u0.x); FFMA2(d[0][1], W0, u0.y);
                    FFMA2(d[0][2], W0, u1.x); FFMA2(d[0][3], W0, u1.y);
                    FFMA2(d[1][0], W1, u0.x); FFMA2(d[1][1], W1, u0.y);
                    FFMA2(d[1][2], W1, u1.x); FFMA2(d[1][3], W1, u1.y);
                    FFMA2(d[2][0], W2, u0.x); FFMA2(d[2][1], W2, u0.y);
                    FFMA2(d[2][2], W2, u1.x); FFMA2(d[2][3], W2, u1.y);
                    FFMA2(d[3][0], W3, u0.x); FFMA2(d[3][1], W3, u0.y);
                    FFMA2(d[3][2], W3, u1.x); FFMA2(d[3][3], W3, u1.y);
                }
            }
#pragma unroll
            for (int ci = 0; ci < 4; ci++)
#pragma unroll
                for (int bi = 0; bi < 4; bi++) {
                    float lo, hi; UNPACK2(lo, hi, d[ci][bi]);
                    lo = fmaxf(lo, 0.f); hi = fmaxf(hi, 0.f);
                    unsigned long long m; PACKAB(m, lo, hi);
                    ADD2(acc2[ci][bi], m);
                }
        }
    }
    __syncthreads();

    // ---- cross-warp reduce (8 j-streams -> one partial per (b,c)) ----------
    float4* rs = (float4*)smem_raw;       // [w][16 b][16 c-quads] = 16KB
#pragma unroll
    for (int bp = 0; bp < 4; bp++) {
        float a0, a1, b1v, b2v, c1, c2, d1, d2;
        UNPACK2(a0, a1, acc2[0][bp]);
        UNPACK2(b1v, b2v, acc2[1][bp]);
        UNPACK2(c1, c2, acc2[2][bp]);
        UNPACK2(d1, d2, acc2[3][bp]);
        rs[w * 256 + (bh * 8 + 2 * bp) * 16 + qd]     = make_float4(a0, b1v, c1, d1);
        rs[w * 256 + (bh * 8 + 2 * bp + 1) * 16 + qd] = make_float4(a1, b2v, c2, d2);
    }
    __syncthreads();

    int ob  = tid >> 4;
    int oc4 = tid & 15;
    float4 v = rs[ob * 16 + oc4];
#pragma unroll
    for (int ww = 1; ww < 8; ww++) {
        float4 u = rs[ww * 256 + ob * 16 + oc4];
        v.x += u.x; v.y += u.y; v.z += u.z; v.w += u.w;
    }
    int b = bchunk * 16 + ob;
    if (b < B)
        *(float4*)(g_part + ((size_t)r * BMAX + b) * COUT + oc4 * 4) = v;
}

// ---- final: sum partials over r + GAP mean + FC ----------------------------
__global__ void fc_kernel(const float* __restrict__ fw,
                          const float* __restrict__ fb,
                          float* __restrict__ out, int B) {
    __shared__ float sm[4][COUT];
    int b = blockIdx.x;
    int tid = threadIdx.x;
    int c = tid & 63, pg = tid >> 6;
    float sum = 0.f;
    for (int rr = pg; rr < CONV_OUT; rr += 4)
        sum += g_part[((size_t)rr * BMAX + b) * COUT + c];
    sm[pg][c] = sum;
    __syncthreads();
    if (tid < COUT)
        sm[0][tid] += sm[1][tid] + sm[2][tid] + sm[3][tid];
    __syncthreads();
    if (tid < 5) {
        const float inv = 1.0f / (float)(CONV_OUT * CONV_OUT);
        float accv = fb[tid];
#pragma unroll 8
        for (int c2 = 0; c2 < COUT; c2++)
            accv = fmaf(sm[0][c2] * inv, fw[tid * 64 + c2], accv);
        out[b * 5 + tid] = accv;
    }
}

// ---------------------------------------------------------------------------
extern "C" void kernel_launch(void* const* d_in, const int* in_sizes, int n_in,
                              void* d_out, int out_size) {
    const float* x      = (const float*)d_in[0];
    const float* conv_w = (const float*)d_in[1];
    const float* conv_b = (const float*)d_in[2];
    const float* fc_w   = (const float*)d_in[3];
    const float* fc_b   = (const float*)d_in[4];
    float*       out    = (float*)d_out;

    int B = in_sizes[0] / SIGLEN;
    if (B > BMAX) B = BMAX;

    cudaFuncSetAttribute(tap_kernel,
                         cudaFuncAttributeMaxDynamicSharedMemorySize, 32768);

    int prep_total = PHI_N + AY_N + TW_N;
    prep_kernel<<<(prep_total + 255) / 256, 256>>>(conv_w);

    spec_kernel<<<NPQ, 256>>>(x, B);

    dim3 tgrid(89, 23);
    theta_kernel<<<tgrid, 256>>>();

    tap_kernel<<<CONV_OUT * 16, 256, 32768>>>(conv_b, B);

    fc_kernel<<<B, 256>>>(fc_w, fc_b, out, B);
}

// round 16
// speedup vs baseline: 1.5444x; 1.0673x over previous
#include <cuda_runtime.h>
#include <cuda_bf16.h>
#include <math.h>

#define BMAX     256
#define SIGLEN   178
#define NFR      43
#define NFQ      33
#define NPQ      (NFQ*NFR)
#define COUT     64
#define CONV_OUT 89
#define NSTEP    12          // ceil(89/8) j-steps

#define PHI_N    (89*4*7*64)
#define AY_N     (89*4*7)
#define TW_N     (33*7)

#define SMEM_SPEC_OFF 32768u          // after 2x16KB theta buffers
#define SMEM_TOTAL    (32768 + 11264)

__device__ __align__(16) float g_spec [NPQ * BMAX];          // [p*43+q][b]
__device__ __align__(16) float g_phi  [PHI_N];               // [j][qt][ky][c]
__device__ __align__(16) float g_ay   [AY_N];                // [r][pt][ky]
__device__ __align__(16) float g_twid [33*14];
__device__ __align__(16) __nv_bfloat16 g_thetah[(size_t)89*89*16*64]; // [r][j][tap][c]
__device__ __align__(16) float g_part [(size_t)CONV_OUT * BMAX * COUT]; // [r][b][c]

// ---- shared index helpers --------------------------------------------------
__device__ __forceinline__ int q0raw(int j) {
    float sx = (2 * j - 3 + 0.5f) * (43.0f / 178.0f) - 0.5f;
    sx = fminf(fmaxf(sx, 0.f), 42.f);
    return (int)sx;
}
__device__ __forceinline__ int q0f(int j) { int q = q0raw(j); return q > 39 ? 39 : q; }
__device__ __forceinline__ int p0f(int r) {
    float sy = (2 * r - 3 + 0.5f) * (33.0f / 178.0f) - 0.5f;
    sy = fminf(fmaxf(sy, 0.f), 32.f);
    int p = (int)sy; return p > 29 ? 29 : p;
}
__device__ __forceinline__ float bweight(int x, int q) {
    if (x < 0 || x >= 178) return 0.f;
    float sx = fminf(fmaxf((x + 0.5f) * (43.0f / 178.0f) - 0.5f, 0.f), 42.f);
    int x0 = (int)sx; float fx = sx - (float)x0; int x1 = min(x0 + 1, 42);
    float w = 0.f;
    if (q == x0) w += 1.f - fx;
    if (q == x1) w += fx;
    return w;
}

#define PACK2(d, x)  asm("mov.b64 %0, {%1, %1};" : "=l"(d) : "f"(x))
#define PACKAB(d, a, b) asm("mov.b64 %0, {%1, %2};" : "=l"(d) : "f"(a), "f"(b))
#define UNPACK2(lo, hi, d) asm("mov.b64 {%0, %1}, %2;" : "=f"(lo), "=f"(hi) : "l"(d))
#define FFMA2(d, a, b) asm("fma.rn.f32x2 %0, %1, %2, %0;" : "+l"(d) : "l"(a), "l"(b))
#define ADD2(acc, v) asm("add.rn.f32x2 %0, %0, %1;" : "+l"(acc) : "l"(v))
// bf16 lo/hi of a 32-bit word -> duplicated f32 pair (prmt shifts bf16<<16)
#define BF2DUP_LO(d, w) asm("{ .reg .b32 t; prmt.b32 t, %1, 0, 0x1044; " \
                            "mov.b64 %0, {t, t}; }" : "=l"(d) : "r"(w))
#define BF2DUP_HI(d, w) asm("{ .reg .b32 t; prmt.b32 t, %1, 0, 0x3244; " \
                            "mov.b64 %0, {t, t}; }" : "=l"(d) : "r"(w))
#define LDSV2U(a0, a1, ad) asm volatile("ld.shared.v2.u32 {%0, %1}, [%2];" \
                                        : "=r"(a0), "=r"(a1) : "r"(ad))
#define LDSV2L(a0, a1, ad) asm volatile("ld.shared.v2.b64 {%0, %1}, [%2];" \
                                        : "=l"(a0), "=l"(a1) : "r"(ad))
#define CPASYNC16(dst, src) asm volatile( \
    "cp.async.cg.shared.global [%0], [%1], 16;" :: "r"(dst), "l"(src))
#define CPCOMMIT() asm volatile("cp.async.commit_group;")
#define CPWAIT0()  asm volatile("cp.async.wait_group 0;")

// ---- prep ------------------------------------------------------------------
__global__ void prep_kernel(const float* __restrict__ w) {
    int t = blockIdx.x * blockDim.x + threadIdx.x;
    if (t < PHI_N) {
        int c  = t & 63;
        int u  = t >> 6;
        int ky = u % 7;  u /= 7;
        int qt = u & 3;
        int j  = u >> 2;
        int q  = q0f(j) + qt;
        const float* wc = w + c * 147 + ky * 7;
        float a = 0.f;
#pragma unroll
        for (int kx = 0; kx < 7; kx++) {
            float ws = wc[kx] + wc[49 + kx] + wc[98 + kx];
            a += ws * bweight(2 * j - 3 + kx, q);
        }
        g_phi[((j * 4 + qt) * 7 + ky) * 64 + c] = a;
    } else if (t < PHI_N + AY_N) {
        int t2 = t - PHI_N;
        int r = t2 / 28, rem = t2 % 28, pt = rem / 7, ky = rem % 7;
        int y = 2 * r - 3 + ky;
        float wgt = 0.f;
        if (y >= 0 && y < 178) {
            float sy = fminf(fmaxf((y + 0.5f) * (33.0f / 178.0f) - 0.5f, 0.f), 32.f);
            int y0 = (int)sy; float fy = sy - (float)y0; int y1 = min(y0 + 1, 32);
            int p = p0f(r) + pt;
            if (p == y0) wgt += 1.f - fy;
            if (p == y1) wgt += fy;
        }
        g_ay[t2] = wgt;
    } else if (t < PHI_N + AY_N + TW_N) {
        int t3 = t - PHI_N - AY_N;
        int k = t3 / 7, n = 1 + t3 % 7;
        float sn, cs;
        sincospif((float)(k * n) * (1.0f / 32.0f), &sn, &cs);
        g_twid[k * 14 + (n - 1) * 2]     = cs;
        g_twid[k * 14 + (n - 1) * 2 + 1] = sn;
    }
}

// ---- spectrogram -----------------------------------------------------------
__global__ void spec_kernel(const float* __restrict__ x, int B) {
    int pq = blockIdx.x;
    int b  = threadIdx.x;
    if (b >= B) return;
    int k  = pq / NFR;
    int fr = pq % NFR;

    const float* s = x + b * SIGLEN + fr * 4;
    float v[8];
    float mean = 0.f;
#pragma unroll
    for (int n = 0; n < 8; n++) { v[n] = s[n]; mean += v[n]; }
    mean *= 0.125f;

    const float* tw = g_twid + k * 14;
    float re = 0.f, im = 0.f;
#pragma unroll
    for (int n = 1; n < 8; n++) {
        float f = v[n] - mean;
        re = fmaf(f, tw[(n - 1) * 2], re);
        im = fmaf(f, -tw[(n - 1) * 2 + 1], im);
    }
    const float SCALE = sqrtf(1.0f / (178.0f * 7.0f));
    g_spec[pq * BMAX + b] = sqrtf(re * re + im * im) * SCALE;
}

// ---- theta: Theta[r][j][tap][c] in bf16, tap = pt*4+qt ---------------------
__global__ void theta_kernel() {
    int j  = blockIdx.x;
    int r0 = blockIdx.y * 4;
    int tid = threadIdx.x;
    int c = tid & 63, qt = tid >> 6;

    float f[7];
#pragma unroll
    for (int ky = 0; ky < 7; ky++)
        f[ky] = g_phi[((j * 4 + qt) * 7 + ky) * 64 + c];

#pragma unroll
    for (int rr = 0; rr < 4; rr++) {
        int r = r0 + rr;
        if (r >= CONV_OUT) break;
        const float* ay = g_ay + r * 28;
        __nv_bfloat16* dst = g_thetah + (size_t)(r * 89 + j) * 1024;
#pragma unroll
        for (int pt = 0; pt < 4; pt++) {
            float th = 0.f;
#pragma unroll
            for (int ky = 0; ky < 7; ky++)
                th = fmaf(ay[pt * 7 + ky], f[ky], th);
            dst[(pt * 4 + qt) * 64 + c] = __float2bfloat16(th);
        }
    }
}

// ---- main tap: cp.async bf16-Θ pipeline + smem spec window (LDG/STS) -------
// block = (r, 16 batches); warp w handles j = step*8 + w.
__global__ void __launch_bounds__(256, 2)
tap_kernel(const float* __restrict__ bias, int B) {
    extern __shared__ float smem_raw[];   // [0,32K) theta 2x16KB, [32K,43K) spec
    int tid  = threadIdx.x;
    int lane = tid & 31, w = tid >> 5;
    int qd   = lane & 15, bh = lane >> 4;

    int item   = blockIdx.x;              // r * 16 + bchunk
    int r      = item >> 4;
    int bchunk = item & 15;
    int c0     = qd * 4;

    unsigned sb;
    asm("{ .reg .u64 t; cvta.to.shared.u64 t, %1; cvt.u32.u64 %0, t; }"
        : "=r"(sb) : "l"(smem_raw));

    int p0 = p0f(r);

    float4 b4 = *(const float4*)(bias + c0);
    unsigned long long bb[4];
    PACK2(bb[0], b4.x); PACK2(bb[1], b4.y);
    PACK2(bb[2], b4.z); PACK2(bb[3], b4.w);

    unsigned long long acc2[4][4];
#pragma unroll
    for (int ci = 0; ci < 4; ci++)
#pragma unroll
        for (int bi = 0; bi < 4; bi++) acc2[ci][bi] = 0ull;

    const char* tbase = (const char*)(g_thetah + (size_t)r * (89 * 1024));

    // Θ stage: 8 slabs x 2KB = 16KB/buffer; thread stages 4x16B
#define STAGE(s, buf) do {                                                  \
        int _s = (s);                                                       \
        _Pragma("unroll")                                                   \
        for (int r4 = 0; r4 < 4; r4++) {                                    \
            int ch = r4 * 256 + tid;                                        \
            int k = ch >> 7, inner = (ch & 127) * 16;                       \
            int jk = _s * 8 + k;                                            \
            if (jk < CONV_OUT)                                              \
                CPASYNC16(sb + (unsigned)((buf) * 16384 + ch * 16),         \
                          tbase + (size_t)jk * 2048 + inner);               \
        }                                                                   \
    } while (0)

    STAGE(0, 0); CPCOMMIT();

    // spec window stage (once, plain LDG.128 + STS.128):
    // 172 rows x 16 floats for this bchunk = 688 float4 chunks.
    {
        float4* sdst = (float4*)(smem_raw + SMEM_SPEC_OFF / 4);
        const float* spsrc = g_spec + (size_t)(p0 * NFR) * BMAX + bchunk * 16;
#pragma unroll
        for (int r3 = 0; r3 < 3; r3++) {
            int i = r3 * 256 + tid;
            if (i < 688) {
                int row = i >> 2, col4 = i & 3;
                sdst[i] = __ldg((const float4*)(spsrc + (size_t)row * BMAX) + col4);
            }
        }
    }

    for (int s = 0; s < NSTEP; s++) {
        CPWAIT0();
        __syncthreads();                  // also publishes the spec STS (s==0)
        if (s + 1 < NSTEP) { STAGE(s + 1, (s + 1) & 1); CPCOMMIT(); }

        int j = s * 8 + w;
        if (j < CONV_OUT) {
            int q0 = q0f(j);
            // spec base for this j: row = pt*43 + q0 + qt, 64B rows
            unsigned specb = sb + SMEM_SPEC_OFF + (unsigned)(q0 * 64 + bh * 32);
            unsigned slab = sb + (unsigned)(((s & 1) * 16384) + w * 2048 + qd * 8);

            unsigned long long d[4][4];
#pragma unroll
            for (int ci = 0; ci < 4; ci++)
#pragma unroll
                for (int bi = 0; bi < 4; bi++) d[ci][bi] = bb[ci];

#pragma unroll
            for (int pt = 0; pt < 4; pt++) {
#pragma unroll
                for (int qt = 0; qt < 4; qt++) {
                    int t = pt * 4 + qt;
                    unsigned w0_, w1_;                   // 4 bf16 channels
                    LDSV2U(w0_, w1_, slab + (unsigned)(t * 128));
                    unsigned sad = specb + (unsigned)((pt * NFR + qt) * 64);
                    unsigned long long u0x, u0y, u1x, u1y;
                    LDSV2L(u0x, u0y, sad);
                    LDSV2L(u1x, u1y, sad + 16u);
                    unsigned long long W0, W1, W2, W3;
                    BF2DUP_LO(W0, w0_); BF2DUP_HI(W1, w0_);
                    BF2DUP_LO(W2, w1_); BF2DUP_HI(W3, w1_);
                    FFMA2(d[0][0], W0, u0x); FFMA2(d[0][1], W0, u0y);
                    FFMA2(d[0][2], W0, u1x); FFMA2(d[0][3], W0, u1y);
                    FFMA2(d[1][0], W1, u0x); FFMA2(d[1][1], W1, u0y);
                    FFMA2(d[1][2], W1, u1x); FFMA2(d[1][3], W1, u1y);
                    FFMA2(d[2][0], W2, u0x); FFMA2(d[2][1], W2, u0y);
                    FFMA2(d[2][2], W2, u1x); FFMA2(d[2][3], W2, u1y);
                    FFMA2(d[3][0], W3, u0x); FFMA2(d[3][1], W3, u0y);
                    FFMA2(d[3][2], W3, u1x); FFMA2(d[3][3], W3, u1y);
                }
            }
#pragma unroll
            for (int ci = 0; ci < 4; ci++)
#pragma unroll
                for (int bi = 0; bi < 4; bi++) {
                    float lo, hi; UNPACK2(lo, hi, d[ci][bi]);
                    lo = fmaxf(lo, 0.f); hi = fmaxf(hi, 0.f);
                    unsigned long long m; PACKAB(m, lo, hi);
                    ADD2(acc2[ci][bi], m);
                }
        }
    }
    __syncthreads();

    // ---- cross-warp reduce (8 j-streams -> one partial per (b,c)) ----------
    float4* rs = (float4*)smem_raw;       // [w][16 b][16 c-quads] = 16KB
#pragma unroll
    for (int bp = 0; bp < 4; bp++) {
        float a0, a1, b1v, b2v, c1, c2, d1, d2;
        UNPACK2(a0, a1, acc2[0][bp]);
        UNPACK2(b1v, b2v, acc2[1][bp]);
        UNPACK2(c1, c2, acc2[2][bp]);
        UNPACK2(d1, d2, acc2[3][bp]);
        rs[w * 256 + (bh * 8 + 2 * bp) * 16 + qd]     = make_float4(a0, b1v, c1, d1);
        rs[w * 256 + (bh * 8 + 2 * bp + 1) * 16 + qd] = make_float4(a1, b2v, c2, d2);
    }
    __syncthreads();

    int ob  = tid >> 4;
    int oc4 = tid & 15;
    float4 v = rs[ob * 16 + oc4];
#pragma unroll
    for (int ww = 1; ww < 8; ww++) {
        float4 u = rs[ww * 256 + ob * 16 + oc4];
        v.x += u.x; v.y += u.y; v.z += u.z; v.w += u.w;
    }
    int b = bchunk * 16 + ob;
    if (b < B)
        *(float4*)(g_part + ((size_t)r * BMAX + b) * COUT + oc4 * 4) = v;
}

// ---- final: sum partials over r + GAP mean + FC ----------------------------
__global__ void fc_kernel(const float* __restrict__ fw,
                          const float* __restrict__ fb,
                          float* __restrict__ out, int B) {
    __shared__ float sm[4][COUT];
    int b = blockIdx.x;
    int tid = threadIdx.x;
    int c = tid & 63, pg = tid >> 6;
    float sum = 0.f;
    for (int rr = pg; rr < CONV_OUT; rr += 4)
        sum += g_part[((size_t)rr * BMAX + b) * COUT + c];
    sm[pg][c] = sum;
    __syncthreads();
    if (tid < COUT)
        sm[0][tid] += sm[1][tid] + sm[2][tid] + sm[3][tid];
    __syncthreads();
    if (tid < 5) {
        const float inv = 1.0f / (float)(CONV_OUT * CONV_OUT);
        float accv = fb[tid];
#pragma unroll 8
        for (int c2 = 0; c2 < COUT; c2++)
            accv = fmaf(sm[0][c2] * inv, fw[tid * 64 + c2], accv);
        out[b * 5 + tid] = accv;
    }
}

// ---------------------------------------------------------------------------
extern "C" void kernel_launch(void* const* d_in, const int* in_sizes, int n_in,
                              void* d_out, int out_size) {
    const float* x      = (const float*)d_in[0];
    const float* conv_w = (const float*)d_in[1];
    const float* conv_b = (const float*)d_in[2];
    const float* fc_w   = (const float*)d_in[3];
    const float* fc_b   = (const float*)d_in[4];
    float*       out    = (float*)d_out;

    int B = in_sizes[0] / SIGLEN;
    if (B > BMAX) B = BMAX;

    cudaFuncSetAttribute(tap_kernel,
                         cudaFuncAttributeMaxDynamicSharedMemorySize, SMEM_TOTAL);

    int prep_total = PHI_N + AY_N + TW_N;
    prep_kernel<<<(prep_total + 255) / 256, 256>>>(conv_w);

    spec_kernel<<<NPQ, 256>>>(x, B);

    dim3 tgrid(89, 23);
    theta_kernel<<<tgrid, 256>>>();

    tap_kernel<<<CONV_OUT * 16, 256, SMEM_TOTAL>>>(conv_b, B);

    fc_kernel<<<B, 256>>>(fc_w, fc_b, out, B);
}

// round 17
// speedup vs baseline: 1.7487x; 1.1323x over previous
#include <cuda_runtime.h>
#include <cuda_bf16.h>
#include <math.h>

#define BMAX     256
#define SIGLEN   178
#define NFR      43
#define NFQ      33
#define NPQ      (NFQ*NFR)
#define COUT     64
#define CONV_OUT 89
#define NSTEP    12          // ceil(89/8) j-steps

#define PHI_N    (89*4*7*64)
#define AY_N     (89*4*7)
#define TW_N     (33*7)
#define PREP_N   (PHI_N + AY_N + TW_N + 2*CONV_OUT)

#define SMEM_SPEC_OFF 32768u          // after 2x16KB theta buffers
#define SMEM_TOTAL    (32768 + 11264)

__device__ __align__(16) float g_spec [NPQ * BMAX];          // [p*43+q][b]
__device__ __align__(16) float g_phi  [PHI_N];               // [j][qt][ky][c]
__device__ __align__(16) float g_ay   [AY_N];                // [r][pt][ky]
__device__ __align__(16) float g_twid [33*14];
__device__ int   g_qtn [CONV_OUT];                           // q-tap count per j
__device__ int   g_ptn [CONV_OUT];                           // p-tap count per r
__device__ __align__(16) __nv_bfloat16 g_thetah[(size_t)89*89*16*64]; // [r][j][tap][c]
__device__ __align__(16) float g_part [(size_t)CONV_OUT * BMAX * COUT]; // [r][b][c]

// ---- shared index helpers --------------------------------------------------
__device__ __forceinline__ int q0raw(int j) {
    float sx = (2 * j - 3 + 0.5f) * (43.0f / 178.0f) - 0.5f;
    sx = fminf(fmaxf(sx, 0.f), 42.f);
    return (int)sx;
}
__device__ __forceinline__ int q0f(int j) { int q = q0raw(j); return q > 39 ? 39 : q; }
__device__ __forceinline__ int p0f(int r) {
    float sy = (2 * r - 3 + 0.5f) * (33.0f / 178.0f) - 0.5f;
    sy = fminf(fmaxf(sy, 0.f), 32.f);
    int p = (int)sy; return p > 29 ? 29 : p;
}
__device__ __forceinline__ float bweight(int x, int q) {
    if (x < 0 || x >= 178) return 0.f;
    float sx = fminf(fmaxf((x + 0.5f) * (43.0f / 178.0f) - 0.5f, 0.f), 42.f);
    int x0 = (int)sx; float fx = sx - (float)x0; int x1 = min(x0 + 1, 42);
    float w = 0.f;
    if (q == x0) w += 1.f - fx;
    if (q == x1) w += fx;
    return w;
}

#define PACK2(d, x)  asm("mov.b64 %0, {%1, %1};" : "=l"(d) : "f"(x))
#define PACKAB(d, a, b) asm("mov.b64 %0, {%1, %2};" : "=l"(d) : "f"(a), "f"(b))
#define UNPACK2(lo, hi, d) asm("mov.b64 {%0, %1}, %2;" : "=f"(lo), "=f"(hi) : "l"(d))
#define FFMA2(d, a, b) asm("fma.rn.f32x2 %0, %1, %2, %0;" : "+l"(d) : "l"(a), "l"(b))
#define ADD2(acc, v) asm("add.rn.f32x2 %0, %0, %1;" : "+l"(acc) : "l"(v))
// bf16 lo/hi of a 32-bit word -> duplicated f32 pair (prmt shifts bf16<<16)
#define BF2DUP_LO(d, w) asm("{ .reg .b32 t; prmt.b32 t, %1, 0, 0x1044; " \
                            "mov.b64 %0, {t, t}; }" : "=l"(d) : "r"(w))
#define BF2DUP_HI(d, w) asm("{ .reg .b32 t; prmt.b32 t, %1, 0, 0x3244; " \
                            "mov.b64 %0, {t, t}; }" : "=l"(d) : "r"(w))
#define LDSV2U(a0, a1, ad) asm volatile("ld.shared.v2.u32 {%0, %1}, [%2];" \
                                        : "=r"(a0), "=r"(a1) : "r"(ad))
#define LDSV2L(a0, a1, ad) asm volatile("ld.shared.v2.b64 {%0, %1}, [%2];" \
                                        : "=l"(a0), "=l"(a1) : "r"(ad))
#define CPASYNC16(dst, src) asm volatile( \
    "cp.async.cg.shared.global [%0], [%1], 16;" :: "r"(dst), "l"(src))
#define CPCOMMIT() asm volatile("cp.async.commit_group;")
#define CPWAIT0()  asm volatile("cp.async.wait_group 0;")

// ---- prep ------------------------------------------------------------------
__global__ void prep_kernel(const float* __restrict__ w) {
    int t = blockIdx.x * blockDim.x + threadIdx.x;
    if (t < PHI_N) {
        int c  = t & 63;
        int u  = t >> 6;
        int ky = u % 7;  u /= 7;
        int qt = u & 3;
        int j  = u >> 2;
        int q  = q0f(j) + qt;
        const float* wc = w + c * 147 + ky * 7;
        float a = 0.f;
#pragma unroll
        for (int kx = 0; kx < 7; kx++) {
            float ws = wc[kx] + wc[49 + kx] + wc[98 + kx];
            a += ws * bweight(2 * j - 3 + kx, q);
        }
        g_phi[((j * 4 + qt) * 7 + ky) * 64 + c] = a;
    } else if (t < PHI_N + AY_N) {
        int t2 = t - PHI_N;
        int r = t2 / 28, rem = t2 % 28, pt = rem / 7, ky = rem % 7;
        int y = 2 * r - 3 + ky;
        float wgt = 0.f;
        if (y >= 0 && y < 178) {
            float sy = fminf(fmaxf((y + 0.5f) * (33.0f / 178.0f) - 0.5f, 0.f), 32.f);
            int y0 = (int)sy; float fy = sy - (float)y0; int y1 = min(y0 + 1, 32);
            int p = p0f(r) + pt;
            if (p == y0) wgt += 1.f - fy;
            if (p == y1) wgt += fy;
        }
        g_ay[t2] = wgt;
    } else if (t < PHI_N + AY_N + TW_N) {
        int t3 = t - PHI_N - AY_N;
        int k = t3 / 7, n = 1 + t3 % 7;
        float sn, cs;
        sincospif((float)(k * n) * (1.0f / 32.0f), &sn, &cs);
        g_twid[k * 14 + (n - 1) * 2]     = cs;
        g_twid[k * 14 + (n - 1) * 2 + 1] = sn;
    } else if (t < PHI_N + AY_N + TW_N + CONV_OUT) {
        // q-tap count per j
        int j = t - PHI_N - AY_N - TW_N;
        int q0 = q0f(j), qmax = q0;
        for (int kx = 0; kx < 7; kx++) {
            int x = 2 * j - 3 + kx;
            if (x < 0 || x >= 178) continue;
            float sx = fminf(fmaxf((x + 0.5f) * (43.0f / 178.0f) - 0.5f, 0.f), 42.f);
            int x0 = (int)sx; float fx = sx - (float)x0; int x1 = min(x0 + 1, 42);
            int hi = (fx > 0.f) ? x1 : x0;
            if (hi > qmax) qmax = hi;
        }
        int n = qmax - q0 + 1;
        g_qtn[j] = n < 3 ? 3 : (n > 4 ? 4 : n);
    } else if (t < PREP_N) {
        // p-tap count per r
        int r = t - PHI_N - AY_N - TW_N - CONV_OUT;
        int p0 = p0f(r), pmax = p0;
        for (int ky = 0; ky < 7; ky++) {
            int y = 2 * r - 3 + ky;
            if (y < 0 || y >= 178) continue;
            float sy = fminf(fmaxf((y + 0.5f) * (33.0f / 178.0f) - 0.5f, 0.f), 32.f);
            int y0 = (int)sy; float fy = sy - (float)y0; int y1 = min(y0 + 1, 32);
            int hi = (fy > 0.f) ? y1 : y0;
            if (hi > pmax) pmax = hi;
        }
        int n = pmax - p0 + 1;
        g_ptn[r] = n < 3 ? 3 : (n > 4 ? 4 : n);
    }
}

// ---- spectrogram -----------------------------------------------------------
__global__ void spec_kernel(const float* __restrict__ x, int B) {
    int pq = blockIdx.x;
    int b  = threadIdx.x;
    if (b >= B) return;
    int k  = pq / NFR;
    int fr = pq % NFR;

    const float* s = x + b * SIGLEN + fr * 4;
    float v[8];
    float mean = 0.f;
#pragma unroll
    for (int n = 0; n < 8; n++) { v[n] = s[n]; mean += v[n]; }
    mean *= 0.125f;

    const float* tw = g_twid + k * 14;
    float re = 0.f, im = 0.f;
#pragma unroll
    for (int n = 1; n < 8; n++) {
        float f = v[n] - mean;
        re = fmaf(f, tw[(n - 1) * 2], re);
        im = fmaf(f, -tw[(n - 1) * 2 + 1], im);
    }
    const float SCALE = sqrtf(1.0f / (178.0f * 7.0f));
    g_spec[pq * BMAX + b] = sqrtf(re * re + im * im) * SCALE;
}

// ---- theta: Theta[r][j][tap][c] in bf16, tap = pt*4+qt ---------------------
__global__ void theta_kernel() {
    int j  = blockIdx.x;
    int r0 = blockIdx.y * 4;
    int tid = threadIdx.x;
    int c = tid & 63, qt = tid >> 6;

    float f[7];
#pragma unroll
    for (int ky = 0; ky < 7; ky++)
        f[ky] = g_phi[((j * 4 + qt) * 7 + ky) * 64 + c];

#pragma unroll
    for (int rr = 0; rr < 4; rr++) {
        int r = r0 + rr;
        if (r >= CONV_OUT) break;
        const float* ay = g_ay + r * 28;
        __nv_bfloat16* dst = g_thetah + (size_t)(r * 89 + j) * 1024;
#pragma unroll
        for (int pt = 0; pt < 4; pt++) {
            float th = 0.f;
#pragma unroll
            for (int ky = 0; ky < 7; ky++)
                th = fmaf(ay[pt * 7 + ky], f[ky], th);
            dst[(pt * 4 + qt) * 64 + c] = __float2bfloat16(th);
        }
    }
}

// ---- tap inner body: PT x QT taps, fully unrolled --------------------------
template<int PT, int QT>
__device__ __forceinline__ void tap_body(
    unsigned slab, unsigned specb, unsigned long long (&d)[4][4]) {
#pragma unroll
    for (int pt = 0; pt < PT; pt++) {
#pragma unroll
        for (int qt = 0; qt < QT; qt++) {
            int t = pt * 4 + qt;
            unsigned w0_, w1_;                   // 4 bf16 channels
            LDSV2U(w0_, w1_, slab + (unsigned)(t * 128));
            unsigned sad = specb + (unsigned)((pt * NFR + qt) * 64);
            unsigned long long u0x, u0y, u1x, u1y;
            LDSV2L(u0x, u0y, sad);
            LDSV2L(u1x, u1y, sad + 16u);
            unsigned long long W0, W1, W2, W3;
            BF2DUP_LO(W0, w0_); BF2DUP_HI(W1, w0_);
            BF2DUP_LO(W2, w1_); BF2DUP_HI(W3, w1_);
            FFMA2(d[0][0], W0, u0x); FFMA2(d[0][1], W0, u0y);
            FFMA2(d[0][2], W0, u1x); FFMA2(d[0][3], W0, u1y);
            FFMA2(d[1][0], W1, u0x); FFMA2(d[1][1], W1, u0y);
            FFMA2(d[1][2], W1, u1x); FFMA2(d[1][3], W1, u1y);
            FFMA2(d[2][0], W2, u0x); FFMA2(d[2][1], W2, u0y);
            FFMA2(d[2][2], W2, u1x); FFMA2(d[2][3], W2, u1y);
            FFMA2(d[3][0], W3, u0x); FFMA2(d[3][1], W3, u0y);
            FFMA2(d[3][2], W3, u1x); FFMA2(d[3][3], W3, u1y);
        }
    }
}

// ---- main tap: cp.async bf16-Θ pipeline + smem spec + variable taps --------
// block = (r, 16 batches); warp w handles j = step*8 + w.
__global__ void __launch_bounds__(256, 2)
tap_kernel(const float* __restrict__ bias, int B) {
    extern __shared__ float smem_raw[];   // [0,32K) theta 2x16KB, [32K,43K) spec
    int tid  = threadIdx.x;
    int lane = tid & 31, w = tid >> 5;
    int qd   = lane & 15, bh = lane >> 4;

    int item   = blockIdx.x;              // r * 16 + bchunk
    int r      = item >> 4;
    int bchunk = item & 15;
    int c0     = qd * 4;

    unsigned sb;
    asm("{ .reg .u64 t; cvta.to.shared.u64 t, %1; cvt.u32.u64 %0, t; }"
        : "=r"(sb) : "l"(smem_raw));

    int p0  = p0f(r);
    int ptn = g_ptn[r];                   // block-uniform

    float4 b4 = *(const float4*)(bias + c0);
    unsigned long long bb[4];
    PACK2(bb[0], b4.x); PACK2(bb[1], b4.y);
    PACK2(bb[2], b4.z); PACK2(bb[3], b4.w);

    unsigned long long acc2[4][4];
#pragma unroll
    for (int ci = 0; ci < 4; ci++)
#pragma unroll
        for (int bi = 0; bi < 4; bi++) acc2[ci][bi] = 0ull;

    const char* tbase = (const char*)(g_thetah + (size_t)r * (89 * 1024));

    // Θ stage: 8 slabs x 2KB = 16KB/buffer; thread stages 4x16B
#define STAGE(s, buf) do {                                                  \
        int _s = (s);                                                       \
        _Pragma("unroll")                                                   \
        for (int r4 = 0; r4 < 4; r4++) {                                    \
            int ch = r4 * 256 + tid;                                        \
            int k = ch >> 7, inner = (ch & 127) * 16;                       \
            int jk = _s * 8 + k;                                            \
            if (jk < CONV_OUT)                                              \
                CPASYNC16(sb + (unsigned)((buf) * 16384 + ch * 16),         \
                          tbase + (size_t)jk * 2048 + inner);               \
        }                                                                   \
    } while (0)

    STAGE(0, 0); CPCOMMIT();

    // spec window stage (once, plain LDG.128 + STS.128)
    {
        float4* sdst = (float4*)(smem_raw + SMEM_SPEC_OFF / 4);
        const float* spsrc = g_spec + (size_t)(p0 * NFR) * BMAX + bchunk * 16;
#pragma unroll
        for (int r3 = 0; r3 < 3; r3++) {
            int i = r3 * 256 + tid;
            if (i < 688) {
                int row = i >> 2, col4 = i & 3;
                sdst[i] = __ldg((const float4*)(spsrc + (size_t)row * BMAX) + col4);
            }
        }
    }

    for (int s = 0; s < NSTEP; s++) {
        CPWAIT0();
        __syncthreads();                  // also publishes the spec STS (s==0)
        if (s + 1 < NSTEP) { STAGE(s + 1, (s + 1) & 1); CPCOMMIT(); }

        int j = s * 8 + w;
        if (j < CONV_OUT) {
            int q0  = q0f(j);
            int qtn = g_qtn[j];           // warp-uniform
            unsigned specb = sb + SMEM_SPEC_OFF + (unsigned)(q0 * 64 + bh * 32);
            unsigned slab = sb + (unsigned)(((s & 1) * 16384) + w * 2048 + qd * 8);

            unsigned long long d[4][4];
#pragma unroll
            for (int ci = 0; ci < 4; ci++)
#pragma unroll
                for (int bi = 0; bi < 4; bi++) d[ci][bi] = bb[ci];

            if (ptn == 3) {
                if (qtn == 3) tap_body<3, 3>(slab, specb, d);
                else          tap_body<3, 4>(slab, specb, d);
            } else {
                if (qtn == 3) tap_body<4, 3>(slab, specb, d);
                else          tap_body<4, 4>(slab, specb, d);
            }

#pragma unroll
            for (int ci = 0; ci < 4; ci++)
#pragma unroll
                for (int bi = 0; bi < 4; bi++) {
                    float lo, hi; UNPACK2(lo, hi, d[ci][bi]);
                    lo = fmaxf(lo, 0.f); hi = fmaxf(hi, 0.f);
                    unsigned long long m; PACKAB(m, lo, hi);
                    ADD2(acc2[ci][bi], m);
                }
        }
    }
    __syncthreads();

    // ---- cross-warp reduce (8 j-streams -> one partial per (b,c)) ----------
    float4* rs = (float4*)smem_raw;       // [w][16 b][16 c-quads] = 16KB
#pragma unroll
    for (int bp = 0; bp < 4; bp++) {
        float a0, a1, b1v, b2v, c1, c2, d1, d2;
        UNPACK2(a0, a1, acc2[0][bp]);
        UNPACK2(b1v, b2v, acc2[1][bp]);
        UNPACK2(c1, c2, acc2[2][bp]);
        UNPACK2(d1, d2, acc2[3][bp]);
        rs[w * 256 + (bh * 8 + 2 * bp) * 16 + qd]     = make_float4(a0, b1v, c1, d1);
        rs[w * 256 + (bh * 8 + 2 * bp + 1) * 16 + qd] = make_float4(a1, b2v, c2, d2);
    }
    __syncthreads();

    int ob  = tid >> 4;
    int oc4 = tid & 15;
    float4 v = rs[ob * 16 + oc4];
#pragma unroll
    for (int ww = 1; ww < 8; ww++) {
        float4 u = rs[ww * 256 + ob * 16 + oc4];
        v.x += u.x; v.y += u.y; v.z += u.z; v.w += u.w;
    }
    int b = bchunk * 16 + ob;
    if (b < B)
        *(float4*)(g_part + ((size_t)r * BMAX + b) * COUT + oc4 * 4) = v;
}

// ---- final: sum partials over r + GAP mean + FC ----------------------------
__global__ void fc_kernel(const float* __restrict__ fw,
                          const float* __restrict__ fb,
                          float* __restrict__ out, int B) {
    __shared__ float sm[4][COUT];
    int b = blockIdx.x;
    int tid = threadIdx.x;
    int c = tid & 63, pg = tid >> 6;
    float sum = 0.f;
    for (int rr = pg; rr < CONV_OUT; rr += 4)
        sum += g_part[((size_t)rr * BMAX + b) * COUT + c];
    sm[pg][c] = sum;
    __syncthreads();
    if (tid < COUT)
        sm[0][tid] += sm[1][tid] + sm[2][tid] + sm[3][tid];
    __syncthreads();
    if (tid < 5) {
        const float inv = 1.0f / (float)(CONV_OUT * CONV_OUT);
        float accv = fb[tid];
#pragma unroll 8
        for (int c2 = 0; c2 < COUT; c2++)
            accv = fmaf(sm[0][c2] * inv, fw[tid * 64 + c2], accv);
        out[b * 5 + tid] = accv;
    }
}

// ---------------------------------------------------------------------------
extern "C" void kernel_launch(void* const* d_in, const int* in_sizes, int n_in,
                              void* d_out, int out_size) {
    const float* x      = (const float*)d_in[0];
    const float* conv_w = (const float*)d_in[1];
    const float* conv_b = (const float*)d_in[2];
    const float* fc_w   = (const float*)d_in[3];
    const float* fc_b   = (const float*)d_in[4];
    float*       out    = (float*)d_out;

    int B = in_sizes[0] / SIGLEN;
    if (B > BMAX) B = BMAX;

    cudaFuncSetAttribute(tap_kernel,
                         cudaFuncAttributeMaxDynamicSharedMemorySize, SMEM_TOTAL);

    prep_kernel<<<(PREP_N + 255) / 256, 256>>>(conv_w);

    spec_kernel<<<NPQ, 256>>>(x, B);

    dim3 tgrid(89, 23);
    theta_kernel<<<tgrid, 256>>>();

    tap_kernel<<<CONV_OUT * 16, 256, SMEM_TOTAL>>>(conv_b, B);

    fc_kernel<<<B, 256>>>(fc_w, fc_b, out, B);
}